// round 7
// baseline (speedup 1.0000x reference)
#include <cuda_runtime.h>
#include <cstdint>
#include <cstddef>

#define NX  256
#define NU  32
#define NY  32
#define BB  16
#define TT  8192
#define LCH 64
#define NCH 128           // TT / LCH chunks per batch
#define ZS  66            // ZT row stride (LCH + 2 pad)
#define KTOT (NX + NU)    // 288 GEMM K
// smem layout (floats): ZT[KTOT][ZS] then R = union{ s_u[64][36], W[288][32] }
#define SM_R      (KTOT * ZS)            // 19008
#define SM_FLOATS (SM_R + KTOT * NY)     // 28224 -> 112896 B

typedef unsigned long long ull;

// -------- device scratch (allocation-free) --------
__device__ float g_BzT[NU * NX];          // [u][n]
__device__ float g_CzT[NX * NY];          // [n][y]
__device__ float g_DT [NU * NY];          // [u][y]
__device__ float g_z0 [BB * NX];
__device__ float g_state[BB * NCH * NX];  // chunk-start states (lookback)
__device__ int   g_flag [BB * NCH];       // ready flags (cleared by prep)

// -------- helpers --------
__device__ __forceinline__ void ffma2(ull& d, ull a, ull b) {
    asm("fma.rn.f32x2 %0, %1, %2, %0;" : "+l"(d) : "l"(a), "l"(b));
}
__device__ __forceinline__ ull addf2(ull a, ull b) {
    ull r; asm("add.rn.f32x2 %0, %1, %2;" : "=l"(r) : "l"(a), "l"(b)); return r;
}
__device__ __forceinline__ ull dup2(float x) {
    ull r; asm("mov.b64 %0, {%1, %1};" : "=l"(r) : "f"(x)); return r;
}
__device__ __forceinline__ ull pack2(float lo, float hi) {
    ull r; asm("mov.b64 %0, {%1, %2};" : "=l"(r) : "f"(lo), "f"(hi)); return r;
}
__device__ __forceinline__ float2 unpk(ull a) {
    float2 f; asm("mov.b64 {%0, %1}, %2;" : "=f"(f.x), "=f"(f.y) : "l"(a)); return f;
}
__device__ __forceinline__ int ld_acq(const int* p) {
    int v; asm volatile("ld.acquire.gpu.b32 %0, [%1];" : "=r"(v) : "l"(p)); return v;
}
__device__ __forceinline__ void st_rel(int* p, int v) {
    asm volatile("st.release.gpu.b32 [%0], %1;" :: "l"(p), "r"(v));
}
union F4U2 { float4 f; ull u[2]; };

// -------- prep: Bz, Cz, z0, D^T + flag clear --------
__global__ __launch_bounds__(256) void prep_kernel(
    const float* __restrict__ x0, const float* __restrict__ Q,
    const float* __restrict__ Bmat, const float* __restrict__ C,
    const float* __restrict__ D)
{
    int idx = blockIdx.x * 256 + threadIdx.x;
    if (idx < BB * NCH) g_flag[idx] = 0;               // clear lookback flags
    if (idx < NU * NX) {                               // BzT[u][n]
        int u = idx >> 8, n = idx & 255;
        float a = 0.f;
        #pragma unroll 8
        for (int i = 0; i < NX; i++) a = fmaf(Q[i * NX + n], Bmat[i * NU + u], a);
        g_BzT[u * NX + n] = a;
    } else if (idx < NU * NX + NY * NX) {              // CzT[n][y]
        int j = idx - NU * NX;
        int y = j >> 8, n = j & 255;
        float a = 0.f;
        #pragma unroll 8
        for (int i = 0; i < NX; i++) a = fmaf(C[y * NX + i], Q[i * NX + n], a);
        g_CzT[n * NY + y] = a;
    } else if (idx < NU * NX + NY * NX + BB * NX) {    // z0[b][n]
        int j = idx - NU * NX - NY * NX;
        int b = j >> 8, n = j & 255;
        float a = 0.f;
        #pragma unroll 8
        for (int i = 0; i < NX; i++) a = fmaf(x0[b * NX + i], Q[i * NX + n], a);
        g_z0[b * NX + n] = a;
    } else if (idx < NU * NX + NY * NX + BB * NX + NU * NY) {  // DT[u][y]
        int j = idx - NU * NX - NY * NX - BB * NX;
        int u = j >> 5, y = j & 31;
        g_DT[u * NY + y] = D[y * NU + u];
    }
}

// -------- fused main: v-compute + lookback scan + GEMM, one CTA per chunk --------
__global__ __launch_bounds__(256, 2) void main_kernel(
    const float* __restrict__ u, const float* __restrict__ lam,
    float* __restrict__ y)
{
    extern __shared__ float sm[];
    float* ZT = sm;              // [288][66]: rows 0-255 = v->z per mode, 256-287 = u^T
    float* R  = sm + SM_R;       // phase 1-2: s_u[64][36]; phase 3+: W[288][32]

    int bid = blockIdx.x;
    int b   = bid >> 7;          // / NCH
    int c   = bid & (NCH - 1);
    int tid = threadIdx.x;
    const size_t chunk = (size_t)b * TT + (size_t)c * LCH;
    const float* ub = u + chunk * NU;

    // ---- phase 1: u chunk -> s_u (padded rows of 36) ----
    #pragma unroll
    for (int i = 0; i < 8; i++) {
        int e = tid + i * 256;                   // coalesced gmem read
        int t = e >> 5, uu = e & 31;
        R[36 * t + uu] = ub[e];
    }
    // per-thread constants (overlap with loads)
    ull bzp[16];                                 // packed Bz row for mode tid
    #pragma unroll
    for (int k = 0; k < 16; k++)
        bzp[k] = pack2(g_BzT[(2 * k) * NX + tid], g_BzT[(2 * k + 1) * NX + tid]);
    float lamn = lam[tid];
    float lamL = lamn;
    #pragma unroll
    for (int i = 0; i < 6; i++) lamL *= lamL;    // lam^64
    __syncthreads();

    // ---- phase 2: transpose u into ZT rows 256..287 ----
    #pragma unroll
    for (int i = 0; i < 8; i++) {
        int e = tid + i * 256;
        int uu = e & 31, t = e >> 5;
        ZT[(NX + uu) * ZS + t] = R[36 * t + uu];
    }

    // ---- phase 3: v-compute + Horner w (ZT row tid <- v) ----
    float w = 0.f;
    float* zr = ZT + tid * ZS;
    #pragma unroll 2
    for (int t = 0; t < LCH; t++) {
        const float4* uu4 = (const float4*)(R + 36 * t);   // broadcast, 16B-aligned
        ull a0 = 0, a1 = 0, a2 = 0, a3 = 0;
        #pragma unroll
        for (int k4 = 0; k4 < 8; k4++) {
            F4U2 q; q.f = uu4[k4];
            if (k4 & 1) { ffma2(a2, bzp[2 * k4], q.u[0]); ffma2(a3, bzp[2 * k4 + 1], q.u[1]); }
            else        { ffma2(a0, bzp[2 * k4], q.u[0]); ffma2(a1, bzp[2 * k4 + 1], q.u[1]); }
        }
        a0 = addf2(a0, a2); a1 = addf2(a1, a3); a0 = addf2(a0, a1);
        float2 f = unpk(a0);
        float v = f.x + f.y;
        w = fmaf(lamn, w, v);
        zr[t] = v;
    }
    __syncthreads();                             // s_u dead after this

    // ---- phase 4: W = [Cz; D^T] into R (overwrites s_u) ----
    #pragma unroll
    for (int i = 0; i < 36; i++) {
        int e = tid + i * 256;
        R[e] = (e < NX * NY) ? g_CzT[e] : g_DT[e - NX * NY];
    }

    // ---- phase 5: lookback chain ----
    float S;
    if (c == 0) {
        S = g_z0[b * NX + tid];
    } else {
        if (tid == 0) {
            while (ld_acq(&g_flag[b * NCH + c]) == 0) __nanosleep(64);
        }
        __syncthreads();
        S = g_state[((size_t)b * NCH + c) * NX + tid];
    }
    if (c + 1 < NCH) {
        g_state[((size_t)b * NCH + c + 1) * NX + tid] = fmaf(lamL, S, w);
        __threadfence();
    }
    __syncthreads();
    if (tid == 0 && c + 1 < NCH) st_rel(&g_flag[b * NCH + c + 1], 1);

    // ---- phase 6: in-place scan (v -> z_prev) ----
    float x = S;
    #pragma unroll 8
    for (int t = 0; t < LCH; t++) {
        float vt = zr[t];
        zr[t] = x;                               // z_prev BEFORE step t
        x = fmaf(lamn, x, vt);
    }
    __syncthreads();

    // ---- phase 7: GEMM  Y[64t x 32y] = ZT^T (K=288) * W ----
    int tg = tid & 31;           // t-pair = {2tg, 2tg+1}
    int yg = tid >> 5;           // y quad = [4yg, 4yg+4)
    ull a00 = 0, a01 = 0, a10 = 0, a11 = 0;
    const float* zp = ZT + 2 * tg;
    const float* wp = R + 4 * yg;
    #pragma unroll 4
    for (int k = 0; k < KTOT; k++) {
        float2 z2 = *(const float2*)(zp + k * ZS);       // 2 t's (aligned: 66k even)
        F4U2 wv; wv.f = *(const float4*)(wp + k * NY);   // broadcast within warp
        ull zd0 = dup2(z2.x), zd1 = dup2(z2.y);
        ffma2(a00, zd0, wv.u[0]); ffma2(a01, zd0, wv.u[1]);
        ffma2(a10, zd1, wv.u[0]); ffma2(a11, zd1, wv.u[1]);
    }

    float* yp = y + chunk * NY;
    float2 f00 = unpk(a00), f01 = unpk(a01), f10 = unpk(a10), f11 = unpk(a11);
    *(float4*)(yp + (size_t)(2 * tg) * NY + 4 * yg) =
        make_float4(f00.x, f00.y, f01.x, f01.y);
    *(float4*)(yp + (size_t)(2 * tg + 1) * NY + 4 * yg) =
        make_float4(f10.x, f10.y, f11.x, f11.y);
}

// -------- launch --------
extern "C" void kernel_launch(void* const* d_in, const int* in_sizes, int n_in,
                              void* d_out, int out_size)
{
    const float* x0   = (const float*)d_in[0];
    const float* u    = (const float*)d_in[1];
    const float* Q    = (const float*)d_in[2];
    const float* lam  = (const float*)d_in[3];
    const float* Bmat = (const float*)d_in[4];
    const float* C    = (const float*)d_in[5];
    const float* D    = (const float*)d_in[6];
    float* y = (float*)d_out;
    (void)in_sizes; (void)n_in; (void)out_size;

    static int attr_set = 0;
    if (!attr_set) {
        cudaFuncSetAttribute(main_kernel,
                             cudaFuncAttributeMaxDynamicSharedMemorySize,
                             SM_FLOATS * (int)sizeof(float));
        attr_set = 1;
    }

    prep_kernel<<<84, 256>>>(x0, Q, Bmat, C, D);
    main_kernel<<<BB * NCH, 256, SM_FLOATS * sizeof(float)>>>(u, lam, y);
}

// round 8
// speedup vs baseline: 3.5402x; 3.5402x over previous
#include <cuda_runtime.h>
#include <cstdint>
#include <cstddef>

#define NX  256
#define NU  32
#define NY  32
#define BB  16
#define TT  8192
#define LCH 64            // chunk length (both pass1 and pass3)
#define NCH 128           // TT / LCH
#define ZS  66            // ZT row stride (LCH + 2 pad)
#define KTOT (NX + NU)    // 288 GEMM K dimension
#define SM_W      (KTOT * ZS)            // 19008 floats
#define SM_FLOATS (SM_W + KTOT * NY)     // 28224 floats -> 112896 B

typedef unsigned long long ull;

// -------- device scratch (allocation-free) --------
__device__ float g_BzT[NU * NX];          // [u][n]
__device__ float g_CzT[NX * NY];          // [n][y]
__device__ float g_DT [NU * NY];          // [u][y]
__device__ float g_z0 [BB * NX];
__device__ float g_w  [BB * NCH * NX];    // per-chunk Horner sums
__device__ float g_ss [BB * NCH * NX];    // chunk-start states
__device__ float g_v  [(size_t)BB * TT * NX];   // 128 MB

// -------- f32x2 helpers --------
__device__ __forceinline__ void ffma2(ull& d, ull a, ull b) {
    asm("fma.rn.f32x2 %0, %1, %2, %0;" : "+l"(d) : "l"(a), "l"(b));
}
__device__ __forceinline__ ull addf2(ull a, ull b) {
    ull r; asm("add.rn.f32x2 %0, %1, %2;" : "=l"(r) : "l"(a), "l"(b)); return r;
}
__device__ __forceinline__ ull dup2(float x) {
    ull r; asm("mov.b64 %0, {%1, %1};" : "=l"(r) : "f"(x)); return r;
}
__device__ __forceinline__ ull pack2(float lo, float hi) {
    ull r; asm("mov.b64 %0, {%1, %2};" : "=l"(r) : "f"(lo), "f"(hi)); return r;
}
__device__ __forceinline__ float2 unpk(ull a) {
    float2 f; asm("mov.b64 {%0, %1}, %2;" : "=f"(f.x), "=f"(f.y) : "l"(a)); return f;
}
union F4U2 { float4 f; ull u[2]; };

// -------- prep: Bz, Cz, z0, D^T --------
__global__ __launch_bounds__(256) void prep_kernel(
    const float* __restrict__ x0, const float* __restrict__ Q,
    const float* __restrict__ Bmat, const float* __restrict__ C,
    const float* __restrict__ D)
{
    int idx = blockIdx.x * 256 + threadIdx.x;
    if (idx < NU * NX) {                               // BzT[u][n]
        int u = idx >> 8, n = idx & 255;
        float a = 0.f;
        #pragma unroll 8
        for (int i = 0; i < NX; i++) a = fmaf(Q[i * NX + n], Bmat[i * NU + u], a);
        g_BzT[u * NX + n] = a;
    } else if (idx < NU * NX + NY * NX) {              // CzT[n][y]
        int j = idx - NU * NX;
        int y = j >> 8, n = j & 255;
        float a = 0.f;
        #pragma unroll 8
        for (int i = 0; i < NX; i++) a = fmaf(C[y * NX + i], Q[i * NX + n], a);
        g_CzT[n * NY + y] = a;
    } else if (idx < NU * NX + NY * NX + BB * NX) {    // z0[b][n]
        int j = idx - NU * NX - NY * NX;
        int b = j >> 8, n = j & 255;
        float a = 0.f;
        #pragma unroll 8
        for (int i = 0; i < NX; i++) a = fmaf(x0[b * NX + i], Q[i * NX + n], a);
        g_z0[b * NX + n] = a;
    } else if (idx < NU * NX + NY * NX + BB * NX + NU * NY) {  // DT[u][y]
        int j = idx - NU * NX - NY * NX - BB * NX;
        int u = j >> 5, y = j & 31;
        g_DT[u * NY + y] = D[y * NU + u];
    }
}

// -------- pass1: v = Bz u (stored) + per-chunk Horner sum, 64-step chunks --------
__global__ __launch_bounds__(256) void pass1_kernel(
    const float* __restrict__ u, const float* __restrict__ lam)
{
    int b = blockIdx.x >> 7;
    int c = blockIdx.x & (NCH - 1);
    int n = threadIdx.x;

    __shared__ float s_u[LCH * NU];   // 8 KB

    const float4* up4 = (const float4*)(u + ((size_t)b * TT + (size_t)c * LCH) * NU);
    float4* su4 = (float4*)s_u;
    #pragma unroll
    for (int i = 0; i < (LCH * NU / 4) / 256; i++)
        su4[n + i * 256] = up4[n + i * 256];

    ull bzp[NU / 2];                  // packed Bz row pairs for mode n
    #pragma unroll
    for (int k = 0; k < NU / 2; k++)
        bzp[k] = pack2(g_BzT[(2 * k) * NX + n], g_BzT[(2 * k + 1) * NX + n]);
    float lamn = lam[n];
    __syncthreads();

    float w = 0.f;
    float* vout = g_v + ((size_t)b * TT + (size_t)c * LCH) * NX + n;
    #pragma unroll 2
    for (int j = 0; j < LCH; j++) {
        const float4* uu = (const float4*)(s_u + j * NU);
        ull a0 = 0, a1 = 0, a2 = 0, a3 = 0;
        #pragma unroll
        for (int k4 = 0; k4 < 8; k4++) {
            F4U2 q; q.f = uu[k4];
            if (k4 & 1) { ffma2(a2, bzp[2 * k4], q.u[0]); ffma2(a3, bzp[2 * k4 + 1], q.u[1]); }
            else        { ffma2(a0, bzp[2 * k4], q.u[0]); ffma2(a1, bzp[2 * k4 + 1], q.u[1]); }
        }
        a0 = addf2(a0, a2); a1 = addf2(a1, a3); a0 = addf2(a0, a1);
        float2 f = unpk(a0);
        float v = f.x + f.y;
        w = fmaf(lamn, w, v);         // Horner
        vout[(size_t)j * NX] = v;     // coalesced
    }
    g_w[((size_t)b * NCH + c) * NX + n] = w;
}

// -------- chunkscan: chunk-start states (128 links, MLP-16) --------
__global__ __launch_bounds__(256) void chunkscan_kernel(const float* __restrict__ lam)
{
    int b = blockIdx.x;
    int n = threadIdx.x;
    float lamL = lam[n];
    #pragma unroll
    for (int i = 0; i < 6; i++) lamL *= lamL;   // lam^64
    float s = g_z0[b * NX + n];
    const size_t base = (size_t)b * NCH * NX + n;
    for (int cg = 0; cg < NCH / 16; cg++) {
        float wv[16];
        #pragma unroll
        for (int i = 0; i < 16; i++)
            wv[i] = g_w[base + (size_t)(cg * 16 + i) * NX];
        #pragma unroll
        for (int i = 0; i < 16; i++) {
            g_ss[base + (size_t)(cg * 16 + i) * NX] = s;
            s = fmaf(lamL, s, wv[i]);
        }
    }
}

// -------- pass3: scan -> smem ZT, register-tiled f32x2 GEMM, 2 CTAs/SM --------
__global__ __launch_bounds__(256, 2) void pass3_kernel(
    const float* __restrict__ u, const float* __restrict__ lam,
    float* __restrict__ y)
{
    extern __shared__ float sm[];
    float* ZT = sm;               // [288][66]: rows 0-255 z_prev, 256-287 u^T
    float* Wm = sm + SM_W;        // [288][32] = [Cz; D^T]

    int b   = blockIdx.x >> 7;
    int c   = blockIdx.x & (NCH - 1);
    int tid = threadIdx.x;
    const size_t chunk = (size_t)b * TT + (size_t)c * LCH;
    const float* ub = u + chunk * NU;

    // ---- u^T into ZT rows 256..287 (coalesced gmem read) ----
    #pragma unroll
    for (int i = 0; i < 8; i++) {
        int e = tid + i * 256;
        int t = e >> 5, uu = e & 31;
        ZT[(NX + uu) * ZS + t] = ub[e];
    }
    // ---- W = [Cz; D^T] ----
    #pragma unroll
    for (int i = 0; i < 36; i++) {
        int e = tid + i * 256;
        Wm[e] = (e < NX * NY) ? g_CzT[e] : g_DT[e - NX * NY];
    }

    // ---- scan: thread owns mode tid; z_prev into ZT row tid ----
    {
        float lamn = lam[tid];
        float S = g_ss[((size_t)b * NCH + c) * NX + tid];
        const float* vp = g_v + chunk * NX + tid;
        float* zr = ZT + tid * ZS;
        #pragma unroll
        for (int grp = 0; grp < LCH / 16; grp++) {
            float vb[16];
            #pragma unroll
            for (int i = 0; i < 16; i++)                 // MLP=16 coalesced
                vb[i] = vp[(size_t)(grp * 16 + i) * NX];
            #pragma unroll
            for (int i = 0; i < 16; i++) {
                zr[grp * 16 + i] = S;                    // state BEFORE step
                S = fmaf(lamn, S, vb[i]);
            }
        }
    }
    __syncthreads();

    // ---- GEMM: Y[64t x 32y] = ZT^T (K=288) * W,  2t x 4y per thread ----
    int tg = tid & 31;            // t-pair {2tg, 2tg+1}
    int yg = tid >> 5;            // y quad [4yg, 4yg+4)
    ull a00 = 0, a01 = 0, a10 = 0, a11 = 0;
    const float* zp = ZT + 2 * tg;
    const float* wp = Wm + 4 * yg;
    #pragma unroll 4
    for (int k = 0; k < KTOT; k++) {
        float2 z2 = *(const float2*)(zp + k * ZS);       // 2 t's
        F4U2 wv; wv.f = *(const float4*)(wp + k * NY);   // warp-broadcast
        ull zd0 = dup2(z2.x), zd1 = dup2(z2.y);
        ffma2(a00, zd0, wv.u[0]); ffma2(a01, zd0, wv.u[1]);
        ffma2(a10, zd1, wv.u[0]); ffma2(a11, zd1, wv.u[1]);
    }

    float* yp = y + chunk * NY;
    float2 f00 = unpk(a00), f01 = unpk(a01), f10 = unpk(a10), f11 = unpk(a11);
    *(float4*)(yp + (size_t)(2 * tg) * NY + 4 * yg) =
        make_float4(f00.x, f00.y, f01.x, f01.y);
    *(float4*)(yp + (size_t)(2 * tg + 1) * NY + 4 * yg) =
        make_float4(f10.x, f10.y, f11.x, f11.y);
}

// -------- launch --------
extern "C" void kernel_launch(void* const* d_in, const int* in_sizes, int n_in,
                              void* d_out, int out_size)
{
    const float* x0   = (const float*)d_in[0];
    const float* u    = (const float*)d_in[1];
    const float* Q    = (const float*)d_in[2];
    const float* lam  = (const float*)d_in[3];
    const float* Bmat = (const float*)d_in[4];
    const float* C    = (const float*)d_in[5];
    const float* D    = (const float*)d_in[6];
    float* y = (float*)d_out;
    (void)in_sizes; (void)n_in; (void)out_size;

    static int attr_set = 0;
    if (!attr_set) {
        cudaFuncSetAttribute(pass3_kernel,
                             cudaFuncAttributeMaxDynamicSharedMemorySize,
                             SM_FLOATS * (int)sizeof(float));
        attr_set = 1;
    }

    prep_kernel<<<84, 256>>>(x0, Q, Bmat, C, D);
    pass1_kernel<<<BB * NCH, 256>>>(u, lam);
    chunkscan_kernel<<<BB, 256>>>(lam);
    pass3_kernel<<<BB * NCH, 256, SM_FLOATS * sizeof(float)>>>(u, lam, y);
}

// round 9
// speedup vs baseline: 3.9097x; 1.1044x over previous
#include <cuda_runtime.h>
#include <cstdint>
#include <cstddef>

#define NX  256
#define NU  32
#define NY  32
#define BB  16
#define TT  8192
#define LCH 64            // chunk length
#define NCH 128           // TT / LCH
#define ZS  68            // ZT row stride (LCH + 4 pad, float4-aligned)
#define KTOT (NX + NU)    // 288 GEMM K dimension
#define KHALF 144
#define SM_W      (KTOT * ZS)            // 19584 floats
#define SM_FLOATS (SM_W + KTOT * NY)     // 28800 floats -> 115200 B

typedef unsigned long long ull;

// -------- device scratch (allocation-free) --------
__device__ float g_BzT[NU * NX];          // [u][n]
__device__ float g_CzT[NX * NY];          // [n][y]
__device__ float g_DT [NU * NY];          // [u][y]
__device__ float g_z0 [BB * NX];
__device__ float g_w  [BB * NCH * NX];    // per-chunk Horner sums
__device__ float g_ss [BB * NCH * NX];    // chunk-start states
__device__ float g_v  [(size_t)BB * TT * NX];   // 128 MB

// -------- f32x2 helpers --------
__device__ __forceinline__ void ffma2(ull& d, ull a, ull b) {
    asm("fma.rn.f32x2 %0, %1, %2, %0;" : "+l"(d) : "l"(a), "l"(b));
}
__device__ __forceinline__ ull addf2(ull a, ull b) {
    ull r; asm("add.rn.f32x2 %0, %1, %2;" : "=l"(r) : "l"(a), "l"(b)); return r;
}
__device__ __forceinline__ ull dup2(float x) {
    ull r; asm("mov.b64 %0, {%1, %1};" : "=l"(r) : "f"(x)); return r;
}
__device__ __forceinline__ ull pack2(float lo, float hi) {
    ull r; asm("mov.b64 %0, {%1, %2};" : "=l"(r) : "f"(lo), "f"(hi)); return r;
}
__device__ __forceinline__ float2 unpk(ull a) {
    float2 f; asm("mov.b64 {%0, %1}, %2;" : "=f"(f.x), "=f"(f.y) : "l"(a)); return f;
}
union F4U2 { float4 f; ull u[2]; };

// -------- prep: Bz, Cz, z0, D^T (4-way ILP) --------
__global__ __launch_bounds__(256) void prep_kernel(
    const float* __restrict__ x0, const float* __restrict__ Q,
    const float* __restrict__ Bmat, const float* __restrict__ C,
    const float* __restrict__ D)
{
    int idx = blockIdx.x * 256 + threadIdx.x;
    if (idx < NU * NX) {                               // BzT[u][n]
        int u = idx >> 8, n = idx & 255;
        float a0 = 0.f, a1 = 0.f, a2 = 0.f, a3 = 0.f;
        #pragma unroll 4
        for (int i = 0; i < NX; i += 4) {
            a0 = fmaf(Q[(i + 0) * NX + n], Bmat[(i + 0) * NU + u], a0);
            a1 = fmaf(Q[(i + 1) * NX + n], Bmat[(i + 1) * NU + u], a1);
            a2 = fmaf(Q[(i + 2) * NX + n], Bmat[(i + 2) * NU + u], a2);
            a3 = fmaf(Q[(i + 3) * NX + n], Bmat[(i + 3) * NU + u], a3);
        }
        g_BzT[u * NX + n] = (a0 + a1) + (a2 + a3);
    } else if (idx < NU * NX + NY * NX) {              // CzT[n][y]
        int j = idx - NU * NX;
        int y = j >> 8, n = j & 255;
        float a0 = 0.f, a1 = 0.f, a2 = 0.f, a3 = 0.f;
        #pragma unroll 4
        for (int i = 0; i < NX; i += 4) {
            a0 = fmaf(C[y * NX + i + 0], Q[(i + 0) * NX + n], a0);
            a1 = fmaf(C[y * NX + i + 1], Q[(i + 1) * NX + n], a1);
            a2 = fmaf(C[y * NX + i + 2], Q[(i + 2) * NX + n], a2);
            a3 = fmaf(C[y * NX + i + 3], Q[(i + 3) * NX + n], a3);
        }
        g_CzT[n * NY + y] = (a0 + a1) + (a2 + a3);
    } else if (idx < NU * NX + NY * NX + BB * NX) {    // z0[b][n]
        int j = idx - NU * NX - NY * NX;
        int b = j >> 8, n = j & 255;
        float a0 = 0.f, a1 = 0.f, a2 = 0.f, a3 = 0.f;
        #pragma unroll 4
        for (int i = 0; i < NX; i += 4) {
            a0 = fmaf(x0[b * NX + i + 0], Q[(i + 0) * NX + n], a0);
            a1 = fmaf(x0[b * NX + i + 1], Q[(i + 1) * NX + n], a1);
            a2 = fmaf(x0[b * NX + i + 2], Q[(i + 2) * NX + n], a2);
            a3 = fmaf(x0[b * NX + i + 3], Q[(i + 3) * NX + n], a3);
        }
        g_z0[b * NX + n] = (a0 + a1) + (a2 + a3);
    } else if (idx < NU * NX + NY * NX + BB * NX + NU * NY) {  // DT[u][y]
        int j = idx - NU * NX - NY * NX - BB * NX;
        int u = j >> 5, y = j & 31;
        g_DT[u * NY + y] = D[y * NU + u];
    }
}

// -------- pass1: v = Bz u (stored) + per-chunk Horner sum --------
__global__ __launch_bounds__(256) void pass1_kernel(
    const float* __restrict__ u, const float* __restrict__ lam)
{
    int b = blockIdx.x >> 7;
    int c = blockIdx.x & (NCH - 1);
    int n = threadIdx.x;

    __shared__ float s_u[LCH * NU];   // 8 KB

    const float4* up4 = (const float4*)(u + ((size_t)b * TT + (size_t)c * LCH) * NU);
    float4* su4 = (float4*)s_u;
    #pragma unroll
    for (int i = 0; i < (LCH * NU / 4) / 256; i++)
        su4[n + i * 256] = up4[n + i * 256];

    ull bzp[NU / 2];
    #pragma unroll
    for (int k = 0; k < NU / 2; k++)
        bzp[k] = pack2(g_BzT[(2 * k) * NX + n], g_BzT[(2 * k + 1) * NX + n]);
    float lamn = lam[n];
    __syncthreads();

    float w = 0.f;
    float* vout = g_v + ((size_t)b * TT + (size_t)c * LCH) * NX + n;
    #pragma unroll 2
    for (int j = 0; j < LCH; j++) {
        const float4* uu = (const float4*)(s_u + j * NU);
        ull a0 = 0, a1 = 0, a2 = 0, a3 = 0;
        #pragma unroll
        for (int k4 = 0; k4 < 8; k4++) {
            F4U2 q; q.f = uu[k4];
            if (k4 & 1) { ffma2(a2, bzp[2 * k4], q.u[0]); ffma2(a3, bzp[2 * k4 + 1], q.u[1]); }
            else        { ffma2(a0, bzp[2 * k4], q.u[0]); ffma2(a1, bzp[2 * k4 + 1], q.u[1]); }
        }
        a0 = addf2(a0, a2); a1 = addf2(a1, a3); a0 = addf2(a0, a1);
        float2 f = unpk(a0);
        float v = f.x + f.y;
        w = fmaf(lamn, w, v);
        vout[(size_t)j * NX] = v;
    }
    g_w[((size_t)b * NCH + c) * NX + n] = w;
}

// -------- chunkscan --------
__global__ __launch_bounds__(256) void chunkscan_kernel(const float* __restrict__ lam)
{
    int b = blockIdx.x;
    int n = threadIdx.x;
    float lamL = lam[n];
    #pragma unroll
    for (int i = 0; i < 6; i++) lamL *= lamL;   // lam^64
    float s = g_z0[b * NX + n];
    const size_t base = (size_t)b * NCH * NX + n;
    for (int cg = 0; cg < NCH / 16; cg++) {
        float wv[16];
        #pragma unroll
        for (int i = 0; i < 16; i++)
            wv[i] = g_w[base + (size_t)(cg * 16 + i) * NX];
        #pragma unroll
        for (int i = 0; i < 16; i++) {
            g_ss[base + (size_t)(cg * 16 + i) * NX] = s;
            s = fmaf(lamL, s, wv[i]);
        }
    }
}

// -------- pass3: scan -> smem ZT, K-split register-tiled f32x2 GEMM --------
__global__ __launch_bounds__(256, 2) void pass3_kernel(
    const float* __restrict__ u, const float* __restrict__ lam,
    float* __restrict__ y)
{
    extern __shared__ float sm[];
    float* ZT = sm;               // [288][68]: rows 0-255 z_prev, 256-287 u^T
    float* Wm = sm + SM_W;        // [288][32] = [Cz; D^T]

    int b    = blockIdx.x >> 7;
    int c    = blockIdx.x & (NCH - 1);
    int tid  = threadIdx.x;
    int w    = tid >> 5;
    int lane = tid & 31;
    const size_t chunk = (size_t)b * TT + (size_t)c * LCH;
    const float* ub = u + chunk * NU;

    // ---- u^T into ZT rows 256..287 ----
    #pragma unroll
    for (int i = 0; i < 8; i++) {
        int e = tid + i * 256;
        int t = e >> 5, uu = e & 31;
        ZT[(NX + uu) * ZS + t] = ub[e];
    }
    // ---- W = [Cz; D^T] ----
    #pragma unroll
    for (int i = 0; i < 36; i++) {
        int e = tid + i * 256;
        Wm[e] = (e < NX * NY) ? g_CzT[e] : g_DT[e - NX * NY];
    }

    // ---- scan: thread owns mode tid; z_prev into ZT row tid (STS.128, pipelined) ----
    {
        float lamn = lam[tid];
        float S = g_ss[((size_t)b * NCH + c) * NX + tid];
        const float* vp = g_v + chunk * NX + tid;
        float* zr = ZT + tid * ZS;

        float vb[2][16];
        #pragma unroll
        for (int i = 0; i < 16; i++) vb[0][i] = vp[(size_t)i * NX];
        #pragma unroll
        for (int grp = 0; grp < 4; grp++) {
            int cur = grp & 1;
            if (grp < 3) {
                #pragma unroll
                for (int i = 0; i < 16; i++)
                    vb[cur ^ 1][i] = vp[(size_t)((grp + 1) * 16 + i) * NX];
            }
            #pragma unroll
            for (int i = 0; i < 16; i += 4) {
                float4 zq;
                zq.x = S; S = fmaf(lamn, S, vb[cur][i + 0]);
                zq.y = S; S = fmaf(lamn, S, vb[cur][i + 1]);
                zq.z = S; S = fmaf(lamn, S, vb[cur][i + 2]);
                zq.w = S; S = fmaf(lamn, S, vb[cur][i + 3]);
                *(float4*)(zr + grp * 16 + i) = zq;   // conflict-free 4-phase
            }
        }
    }
    __syncthreads();

    // ---- GEMM: Y[64t x 32y] = ZT^T (K=288) * W ----
    // warps 0-3: k in [0,144); warps 4-7: k in [144,288)
    // warp wq covers t in [16wq,16wq+16); thread = 8t x 2y
    int half = w >> 2;
    int wq   = w & 3;
    int th   = lane >> 4;          // t sub-half
    int yp   = lane & 15;          // y pair
    int tb   = 16 * wq + 8 * th;

    ull acc[8];                    // acc[2*tp + yj], tp = t-pair 0..3
    #pragma unroll
    for (int i = 0; i < 8; i++) acc[i] = 0;

    const float* zk = ZT + half * KHALF * ZS + tb;
    const float* wk = Wm + half * KHALF * NY + 2 * yp;
    #pragma unroll 4
    for (int k = 0; k < KHALF; k++) {
        F4U2 zA; zA.f = *(const float4*)(zk);        // t pairs 0,1
        F4U2 zB; zB.f = *(const float4*)(zk + 4);    // t pairs 2,3
        float2 wv = *(const float2*)(wk);
        ull w0 = dup2(wv.x), w1 = dup2(wv.y);
        ffma2(acc[0], zA.u[0], w0); ffma2(acc[1], zA.u[0], w1);
        ffma2(acc[2], zA.u[1], w0); ffma2(acc[3], zA.u[1], w1);
        ffma2(acc[4], zB.u[0], w0); ffma2(acc[5], zB.u[0], w1);
        ffma2(acc[6], zB.u[1], w0); ffma2(acc[7], zB.u[1], w1);
        zk += ZS; wk += NY;
    }

    // ---- combine halves (scratch overlays dead ZT) ----
    __syncthreads();
    ull* red = (ull*)ZT;
    int slot = (wq * 32 + lane) * 17;    // stride-17 ull: 2-way max conflict
    if (half == 1) {
        #pragma unroll
        for (int i = 0; i < 8; i++) red[slot + i] = acc[i];
    }
    __syncthreads();
    if (half == 0) {
        float* yrow = y + chunk * NY;
        #pragma unroll
        for (int tp = 0; tp < 4; tp++) {
            ull a0 = addf2(acc[2 * tp + 0], red[slot + 2 * tp + 0]);
            ull a1 = addf2(acc[2 * tp + 1], red[slot + 2 * tp + 1]);
            float2 f0 = unpk(a0);        // y'=2yp   : (t0, t1)
            float2 f1 = unpk(a1);        // y'=2yp+1 : (t0, t1)
            int t0 = tb + 2 * tp;
            *(float2*)(yrow + (size_t)t0 * NY + 2 * yp) =
                make_float2(f0.x, f1.x);
            *(float2*)(yrow + (size_t)(t0 + 1) * NY + 2 * yp) =
                make_float2(f0.y, f1.y);
        }
    }
}

// -------- launch --------
extern "C" void kernel_launch(void* const* d_in, const int* in_sizes, int n_in,
                              void* d_out, int out_size)
{
    const float* x0   = (const float*)d_in[0];
    const float* u    = (const float*)d_in[1];
    const float* Q    = (const float*)d_in[2];
    const float* lam  = (const float*)d_in[3];
    const float* Bmat = (const float*)d_in[4];
    const float* C    = (const float*)d_in[5];
    const float* D    = (const float*)d_in[6];
    float* y = (float*)d_out;
    (void)in_sizes; (void)n_in; (void)out_size;

    static int attr_set = 0;
    if (!attr_set) {
        cudaFuncSetAttribute(pass3_kernel,
                             cudaFuncAttributeMaxDynamicSharedMemorySize,
                             SM_FLOATS * (int)sizeof(float));
        attr_set = 1;
    }

    prep_kernel<<<84, 256>>>(x0, Q, Bmat, C, D);
    pass1_kernel<<<BB * NCH, 256>>>(u, lam);
    chunkscan_kernel<<<BB, 256>>>(lam);
    pass3_kernel<<<BB * NCH, 256, SM_FLOATS * sizeof(float)>>>(u, lam, y);
}

// round 10
// speedup vs baseline: 3.9325x; 1.0058x over previous
#include <cuda_runtime.h>
#include <cstdint>
#include <cstddef>

#define NX  256
#define NU  32
#define NY  32
#define BB  16
#define TT  8192
#define LCH 64            // chunk length
#define NCH 128           // TT / LCH
#define ZS  68            // pass3 ZT row stride
#define KTOT (NX + NU)    // 288
#define KHALF 144
#define SM_W      (KTOT * ZS)            // 19584 floats
#define SM_FLOATS (SM_W + KTOT * NY)     // 28800 floats -> 115200 B

// pass1 smem layout (floats)
#define P1_BZ 0                          // [32][256]
#define P1_UT (32 * NX)                  // [32][68]
#define P1_V  (P1_UT + 32 * 68)         // [256][68]
#define P1_FLOATS (P1_V + NX * 68)      // 27776 -> 111104 B

typedef unsigned long long ull;

// -------- device scratch (allocation-free) --------
__device__ float g_BzT[NU * NX];          // [u][n]
__device__ float g_CzT[NX * NY];          // [n][y]
__device__ float g_DT [NU * NY];          // [u][y]
__device__ float g_z0 [BB * NX];
__device__ float g_w  [BB * NCH * NX];
__device__ float g_ss [BB * NCH * NX];
__device__ float g_v  [(size_t)BB * TT * NX];   // 128 MB

// -------- f32x2 helpers --------
__device__ __forceinline__ void ffma2(ull& d, ull a, ull b) {
    asm("fma.rn.f32x2 %0, %1, %2, %0;" : "+l"(d) : "l"(a), "l"(b));
}
__device__ __forceinline__ ull addf2(ull a, ull b) {
    ull r; asm("add.rn.f32x2 %0, %1, %2;" : "=l"(r) : "l"(a), "l"(b)); return r;
}
__device__ __forceinline__ ull dup2(float x) {
    ull r; asm("mov.b64 %0, {%1, %1};" : "=l"(r) : "f"(x)); return r;
}
__device__ __forceinline__ float2 unpk(ull a) {
    float2 f; asm("mov.b64 {%0, %1}, %2;" : "=f"(f.x), "=f"(f.y) : "l"(a)); return f;
}
union F4U2 { float4 f; ull u[2]; };

// -------- prep: Bz, Cz, z0, D^T (4-way ILP) --------
__global__ __launch_bounds__(256) void prep_kernel(
    const float* __restrict__ x0, const float* __restrict__ Q,
    const float* __restrict__ Bmat, const float* __restrict__ C,
    const float* __restrict__ D)
{
    int idx = blockIdx.x * 256 + threadIdx.x;
    if (idx < NU * NX) {
        int u = idx >> 8, n = idx & 255;
        float a0 = 0.f, a1 = 0.f, a2 = 0.f, a3 = 0.f;
        #pragma unroll 4
        for (int i = 0; i < NX; i += 4) {
            a0 = fmaf(Q[(i + 0) * NX + n], Bmat[(i + 0) * NU + u], a0);
            a1 = fmaf(Q[(i + 1) * NX + n], Bmat[(i + 1) * NU + u], a1);
            a2 = fmaf(Q[(i + 2) * NX + n], Bmat[(i + 2) * NU + u], a2);
            a3 = fmaf(Q[(i + 3) * NX + n], Bmat[(i + 3) * NU + u], a3);
        }
        g_BzT[u * NX + n] = (a0 + a1) + (a2 + a3);
    } else if (idx < NU * NX + NY * NX) {
        int j = idx - NU * NX;
        int y = j >> 8, n = j & 255;
        float a0 = 0.f, a1 = 0.f, a2 = 0.f, a3 = 0.f;
        #pragma unroll 4
        for (int i = 0; i < NX; i += 4) {
            a0 = fmaf(C[y * NX + i + 0], Q[(i + 0) * NX + n], a0);
            a1 = fmaf(C[y * NX + i + 1], Q[(i + 1) * NX + n], a1);
            a2 = fmaf(C[y * NX + i + 2], Q[(i + 2) * NX + n], a2);
            a3 = fmaf(C[y * NX + i + 3], Q[(i + 3) * NX + n], a3);
        }
        g_CzT[n * NY + y] = (a0 + a1) + (a2 + a3);
    } else if (idx < NU * NX + NY * NX + BB * NX) {
        int j = idx - NU * NX - NY * NX;
        int b = j >> 8, n = j & 255;
        float a0 = 0.f, a1 = 0.f, a2 = 0.f, a3 = 0.f;
        #pragma unroll 4
        for (int i = 0; i < NX; i += 4) {
            a0 = fmaf(x0[b * NX + i + 0], Q[(i + 0) * NX + n], a0);
            a1 = fmaf(x0[b * NX + i + 1], Q[(i + 1) * NX + n], a1);
            a2 = fmaf(x0[b * NX + i + 2], Q[(i + 2) * NX + n], a2);
            a3 = fmaf(x0[b * NX + i + 3], Q[(i + 3) * NX + n], a3);
        }
        g_z0[b * NX + n] = (a0 + a1) + (a2 + a3);
    } else if (idx < NU * NX + NY * NX + BB * NX + NU * NY) {
        int j = idx - NU * NX - NY * NX - BB * NX;
        int u = j >> 5, y = j & 31;
        g_DT[u * NY + y] = D[y * NU + u];
    }
}

// -------- pass1: V[256n x 64t] GEMM -> smem, Horner + coalesced v store --------
__global__ __launch_bounds__(256, 2) void pass1_kernel(
    const float* __restrict__ u, const float* __restrict__ lam)
{
    extern __shared__ float sm[];
    float* s_bz = sm + P1_BZ;     // [32 u][256 n]
    float* s_ut = sm + P1_UT;     // [32 u][68: 64 t + pad]
    float* s_v  = sm + P1_V;      // [256 n][68: 64 t + pad]

    int b   = blockIdx.x >> 7;
    int c   = blockIdx.x & (NCH - 1);
    int tid = threadIdx.x;
    const size_t chunk = (size_t)b * TT + (size_t)c * LCH;
    const float* ub = u + chunk * NU;

    // ---- loads: BzT (float4 coalesced), u^T transpose ----
    #pragma unroll
    for (int i = 0; i < 8; i++)
        ((float4*)s_bz)[tid + i * 256] = ((const float4*)g_BzT)[tid + i * 256];
    #pragma unroll
    for (int i = 0; i < 8; i++) {
        int e = tid + i * 256;
        int t = e >> 5, uu = e & 31;
        s_ut[uu * 68 + t] = ub[e];
    }
    __syncthreads();

    // ---- GEMM: thread tile 8n x 8t, K=32 ----
    int a  = tid >> 3;            // n-block: n in [8a, 8a+8)
    int bq = tid & 7;             // t-block: t in [8bq, 8bq+8)
    ull acc[8][4];                // [n][t-pair]
    #pragma unroll
    for (int i = 0; i < 8; i++)
        #pragma unroll
        for (int j = 0; j < 4; j++) acc[i][j] = 0;

    #pragma unroll 8
    for (int k = 0; k < 32; k++) {
        float4 n0 = *(const float4*)(s_bz + k * NX + 8 * a);
        float4 n1 = *(const float4*)(s_bz + k * NX + 8 * a + 4);
        F4U2 t0; t0.f = *(const float4*)(s_ut + k * 68 + 8 * bq);
        F4U2 t1; t1.f = *(const float4*)(s_ut + k * 68 + 8 * bq + 4);
        float nv[8] = {n0.x, n0.y, n0.z, n0.w, n1.x, n1.y, n1.z, n1.w};
        #pragma unroll
        for (int i = 0; i < 8; i++) {
            ull nd = dup2(nv[i]);
            ffma2(acc[i][0], nd, t0.u[0]);
            ffma2(acc[i][1], nd, t0.u[1]);
            ffma2(acc[i][2], nd, t1.u[0]);
            ffma2(acc[i][3], nd, t1.u[1]);
        }
    }

    // ---- tile -> s_v (2 STS.128 per n-row) ----
    #pragma unroll
    for (int i = 0; i < 8; i++) {
        float2 p0 = unpk(acc[i][0]), p1 = unpk(acc[i][1]);
        float2 p2 = unpk(acc[i][2]), p3 = unpk(acc[i][3]);
        float* row = s_v + (8 * a + i) * 68 + 8 * bq;
        *(float4*)(row)     = make_float4(p0.x, p0.y, p1.x, p1.y);
        *(float4*)(row + 4) = make_float4(p2.x, p2.y, p3.x, p3.y);
    }
    __syncthreads();

    // ---- Horner + v store: thread owns mode tid ----
    {
        float lamn = lam[tid];
        float4 vv[16];
        #pragma unroll
        for (int q = 0; q < 16; q++)           // stride-17 f4-banks: conflict-free
            vv[q] = *(const float4*)(s_v + tid * 68 + 4 * q);
        float w = 0.f;
        #pragma unroll
        for (int q = 0; q < 16; q++) {
            w = fmaf(lamn, w, vv[q].x);
            w = fmaf(lamn, w, vv[q].y);
            w = fmaf(lamn, w, vv[q].z);
            w = fmaf(lamn, w, vv[q].w);
        }
        g_w[((size_t)b * NCH + c) * NX + tid] = w;

        float* vout = g_v + chunk * NX + tid;  // [t][n], coalesced per t
        #pragma unroll
        for (int q = 0; q < 16; q++) {
            vout[(size_t)(4 * q + 0) * NX] = vv[q].x;
            vout[(size_t)(4 * q + 1) * NX] = vv[q].y;
            vout[(size_t)(4 * q + 2) * NX] = vv[q].z;
            vout[(size_t)(4 * q + 3) * NX] = vv[q].w;
        }
    }
}

// -------- chunkscan --------
__global__ __launch_bounds__(256) void chunkscan_kernel(const float* __restrict__ lam)
{
    int b = blockIdx.x;
    int n = threadIdx.x;
    float lamL = lam[n];
    #pragma unroll
    for (int i = 0; i < 6; i++) lamL *= lamL;   // lam^64
    float s = g_z0[b * NX + n];
    const size_t base = (size_t)b * NCH * NX + n;
    for (int cg = 0; cg < NCH / 16; cg++) {
        float wv[16];
        #pragma unroll
        for (int i = 0; i < 16; i++)
            wv[i] = g_w[base + (size_t)(cg * 16 + i) * NX];
        #pragma unroll
        for (int i = 0; i < 16; i++) {
            g_ss[base + (size_t)(cg * 16 + i) * NX] = s;
            s = fmaf(lamL, s, wv[i]);
        }
    }
}

// -------- pass3: unchanged from R9 (validated 83.9 us) --------
__global__ __launch_bounds__(256, 2) void pass3_kernel(
    const float* __restrict__ u, const float* __restrict__ lam,
    float* __restrict__ y)
{
    extern __shared__ float sm[];
    float* ZT = sm;               // [288][68]
    float* Wm = sm + SM_W;        // [288][32]

    int b    = blockIdx.x >> 7;
    int c    = blockIdx.x & (NCH - 1);
    int tid  = threadIdx.x;
    int w    = tid >> 5;
    int lane = tid & 31;
    const size_t chunk = (size_t)b * TT + (size_t)c * LCH;
    const float* ub = u + chunk * NU;

    #pragma unroll
    for (int i = 0; i < 8; i++) {
        int e = tid + i * 256;
        int t = e >> 5, uu = e & 31;
        ZT[(NX + uu) * ZS + t] = ub[e];
    }
    #pragma unroll
    for (int i = 0; i < 36; i++) {
        int e = tid + i * 256;
        Wm[e] = (e < NX * NY) ? g_CzT[e] : g_DT[e - NX * NY];
    }

    {
        float lamn = lam[tid];
        float S = g_ss[((size_t)b * NCH + c) * NX + tid];
        const float* vp = g_v + chunk * NX + tid;
        float* zr = ZT + tid * ZS;

        float vb[2][16];
        #pragma unroll
        for (int i = 0; i < 16; i++) vb[0][i] = vp[(size_t)i * NX];
        #pragma unroll
        for (int grp = 0; grp < 4; grp++) {
            int cur = grp & 1;
            if (grp < 3) {
                #pragma unroll
                for (int i = 0; i < 16; i++)
                    vb[cur ^ 1][i] = vp[(size_t)((grp + 1) * 16 + i) * NX];
            }
            #pragma unroll
            for (int i = 0; i < 16; i += 4) {
                float4 zq;
                zq.x = S; S = fmaf(lamn, S, vb[cur][i + 0]);
                zq.y = S; S = fmaf(lamn, S, vb[cur][i + 1]);
                zq.z = S; S = fmaf(lamn, S, vb[cur][i + 2]);
                zq.w = S; S = fmaf(lamn, S, vb[cur][i + 3]);
                *(float4*)(zr + grp * 16 + i) = zq;
            }
        }
    }
    __syncthreads();

    int half = w >> 2;
    int wq   = w & 3;
    int th   = lane >> 4;
    int yp   = lane & 15;
    int tb   = 16 * wq + 8 * th;

    ull acc[8];
    #pragma unroll
    for (int i = 0; i < 8; i++) acc[i] = 0;

    const float* zk = ZT + half * KHALF * ZS + tb;
    const float* wk = Wm + half * KHALF * NY + 2 * yp;
    #pragma unroll 4
    for (int k = 0; k < KHALF; k++) {
        F4U2 zA; zA.f = *(const float4*)(zk);
        F4U2 zB; zB.f = *(const float4*)(zk + 4);
        float2 wv = *(const float2*)(wk);
        ull w0 = dup2(wv.x), w1 = dup2(wv.y);
        ffma2(acc[0], zA.u[0], w0); ffma2(acc[1], zA.u[0], w1);
        ffma2(acc[2], zA.u[1], w0); ffma2(acc[3], zA.u[1], w1);
        ffma2(acc[4], zB.u[0], w0); ffma2(acc[5], zB.u[0], w1);
        ffma2(acc[6], zB.u[1], w0); ffma2(acc[7], zB.u[1], w1);
        zk += ZS; wk += NY;
    }

    __syncthreads();
    ull* red = (ull*)ZT;
    int slot = (wq * 32 + lane) * 17;
    if (half == 1) {
        #pragma unroll
        for (int i = 0; i < 8; i++) red[slot + i] = acc[i];
    }
    __syncthreads();
    if (half == 0) {
        float* yrow = y + chunk * NY;
        #pragma unroll
        for (int tp = 0; tp < 4; tp++) {
            ull a0 = addf2(acc[2 * tp + 0], red[slot + 2 * tp + 0]);
            ull a1 = addf2(acc[2 * tp + 1], red[slot + 2 * tp + 1]);
            float2 f0 = unpk(a0);
            float2 f1 = unpk(a1);
            int t0 = tb + 2 * tp;
            *(float2*)(yrow + (size_t)t0 * NY + 2 * yp) =
                make_float2(f0.x, f1.x);
            *(float2*)(yrow + (size_t)(t0 + 1) * NY + 2 * yp) =
                make_float2(f0.y, f1.y);
        }
    }
}

// -------- launch --------
extern "C" void kernel_launch(void* const* d_in, const int* in_sizes, int n_in,
                              void* d_out, int out_size)
{
    const float* x0   = (const float*)d_in[0];
    const float* u    = (const float*)d_in[1];
    const float* Q    = (const float*)d_in[2];
    const float* lam  = (const float*)d_in[3];
    const float* Bmat = (const float*)d_in[4];
    const float* C    = (const float*)d_in[5];
    const float* D    = (const float*)d_in[6];
    float* y = (float*)d_out;
    (void)in_sizes; (void)n_in; (void)out_size;

    static int attr_set = 0;
    if (!attr_set) {
        cudaFuncSetAttribute(pass3_kernel,
                             cudaFuncAttributeMaxDynamicSharedMemorySize,
                             SM_FLOATS * (int)sizeof(float));
        cudaFuncSetAttribute(pass1_kernel,
                             cudaFuncAttributeMaxDynamicSharedMemorySize,
                             P1_FLOATS * (int)sizeof(float));
        attr_set = 1;
    }

    prep_kernel<<<84, 256>>>(x0, Q, Bmat, C, D);
    pass1_kernel<<<BB * NCH, 256, P1_FLOATS * sizeof(float)>>>(u, lam);
    chunkscan_kernel<<<BB, 256>>>(lam);
    pass3_kernel<<<BB * NCH, 256, SM_FLOATS * sizeof(float)>>>(u, lam, y);
}